// round 1
// baseline (speedup 1.0000x reference)
#include <cuda_runtime.h>
#include <cstdint>

// ---------------------------------------------------------------------------
// Problem constants (fixed shapes from reference setup_inputs)
// ---------------------------------------------------------------------------
#define EMAX 2048
#define DD   200          // embedding dim
#define CC   50           // conv channels
#define CD   10000        // C*D  (FC reduction length)
#define EPS_BN  1e-5f
#define EPS_COS 1e-8f

// ---------------------------------------------------------------------------
// Scratch (static device globals — no runtime allocation allowed)
// ---------------------------------------------------------------------------
__device__ float g_y[4ull * EMAX * CD];     // conv+bias outputs, 4 decode blocks (328 MB)
__device__ float g_z[4ull * EMAX * DD];     // FC outputs
__device__ float g_stats1[4 * 2 * CC];      // per-block [sum(50), sumsq(50)]
__device__ float g_stats2[4 * 2 * DD];      // per-block [sum(200), sumsq(200)]
__device__ float g_a1k[4 * CD];             // BN1 scale expanded over k
__device__ float g_b1k[4 * CD];             // BN1 shift expanded over k

// ---------------------------------------------------------------------------
// f32x2 packed-FMA helpers (Blackwell sm_103a; FFMA2 only reachable via PTX)
// ---------------------------------------------------------------------------
__device__ __forceinline__ unsigned long long pk2(float lo, float hi) {
    unsigned long long r;
    asm("mov.b64 %0, {%1,%2};" : "=l"(r) : "f"(lo), "f"(hi));
    return r;
}
__device__ __forceinline__ void fma2(unsigned long long& d,
                                     unsigned long long a,
                                     unsigned long long b) {
    asm("fma.rn.f32x2 %0, %1, %2, %0;" : "+l"(d) : "l"(a), "l"(b));
}
__device__ __forceinline__ void unpk2(unsigned long long v, float& lo, float& hi) {
    asm("mov.b64 {%0,%1}, %2;" : "=f"(lo), "=f"(hi) : "l"(v));
}

// ---------------------------------------------------------------------------
// K0: zero the output matrix + reset stat accumulators
// ---------------------------------------------------------------------------
__global__ void zero_kernel(float* __restrict__ out, size_t n) {
    size_t stride = (size_t)gridDim.x * blockDim.x;
    size_t i = (size_t)blockIdx.x * blockDim.x + threadIdx.x;
    size_t n4 = n >> 2;
    float4 z4 = make_float4(0.f, 0.f, 0.f, 0.f);
    float4* o4 = (float4*)out;
    for (size_t j = i; j < n4; j += stride) o4[j] = z4;
    for (size_t j = (n4 << 2) + i; j < n; j += stride) out[j] = 0.f;
    if (blockIdx.x == 0) {
        for (int j = threadIdx.x; j < 4 * 2 * CC; j += blockDim.x) g_stats1[j] = 0.f;
        for (int j = threadIdx.x; j < 4 * 2 * DD; j += blockDim.x) g_stats2[j] = 0.f;
    }
}

// ---------------------------------------------------------------------------
// K1: conv1d (SAME, k=3) + bias, write y, accumulate BN1 stats per channel.
// Grid: (E, 4 decode blocks), 256 threads. Thread t < 200 owns position d=t.
// ---------------------------------------------------------------------------
__global__ void conv_bn_kernel(
    const float* __restrict__ pre_emb, const float* __restrict__ r_emb,
    const float* __restrict__ W2, const float* __restrict__ b2,
    const float* __restrict__ W3, const float* __restrict__ b3,
    const float* __restrict__ W4, const float* __restrict__ b4,
    const int* __restrict__ src_ids, const int* __restrict__ edge_type,
    const int* __restrict__ p1, const int* __restrict__ p2,
    const int* __restrict__ p3, int E)
{
    const int e   = blockIdx.x;
    const int blk = blockIdx.y;
    const int t   = threadIdx.x;

    __shared__ float xs[4][DD + 2];     // zero-padded channels
    __shared__ float ws[CC * 4 * 3];
    __shared__ float bs[CC];
    __shared__ float ssum[CC], ssq[CC];

    int Cin;
    const float* Wp;
    const float* bp;
    int rel[3] = {0, 0, 0};
    if (blk == 0)      { Cin = 2; Wp = W2; bp = b2; rel[0] = p1[e]; }
    else if (blk == 1) { Cin = 3; Wp = W3; bp = b3; rel[0] = p2[2*e]; rel[1] = p2[2*e+1]; }
    else if (blk == 2) { Cin = 4; Wp = W4; bp = b4; rel[0] = p3[3*e]; rel[1] = p3[3*e+1]; rel[2] = p3[3*e+2]; }
    else               { Cin = 2; Wp = W2; bp = b2; rel[0] = edge_type[e]; }

    const int sidx = src_ids[e];
    for (int i = 0; i < Cin; i++) {
        const float* src = (i == 0) ? (pre_emb + (size_t)sidx * DD)
                                    : (r_emb + (size_t)rel[i-1] * DD);
        for (int d = t; d < DD; d += blockDim.x) xs[i][d + 1] = src[d];
    }
    if (t < 4) { xs[t][0] = 0.f; xs[t][DD + 1] = 0.f; }
    const int nw = CC * Cin * 3;
    for (int i = t; i < nw; i += blockDim.x) ws[i] = Wp[i];
    if (t < CC) { bs[t] = bp[t]; ssum[t] = 0.f; ssq[t] = 0.f; }
    __syncthreads();

    float* yout = g_y + ((size_t)blk * E + e) * CD;

    for (int c = 0; c < CC; c++) {
        float val = 0.f;
        if (t < DD) {
            const float* w = &ws[c * Cin * 3];
            float acc = bs[c];
            for (int i = 0; i < Cin; i++) {
                acc = fmaf(w[i*3 + 0], xs[i][t    ], acc);
                acc = fmaf(w[i*3 + 1], xs[i][t + 1], acc);
                acc = fmaf(w[i*3 + 2], xs[i][t + 2], acc);
            }
            yout[c * DD + t] = acc;
            val = acc;
        }
        float v = val, q = val * val;
        #pragma unroll
        for (int off = 16; off; off >>= 1) {
            v += __shfl_down_sync(0xffffffffu, v, off);
            q += __shfl_down_sync(0xffffffffu, q, off);
        }
        if ((t & 31) == 0) { atomicAdd(&ssum[c], v); atomicAdd(&ssq[c], q); }
    }
    __syncthreads();
    if (t < CC)            atomicAdd(&g_stats1[blk * 2 * CC + t], ssum[t]);
    else if (t < 2 * CC)   atomicAdd(&g_stats1[blk * 2 * CC + t], ssq[t - CC]);
}

// ---------------------------------------------------------------------------
// K2: BN1 finalize -> expand per-k scale/shift arrays. Grid: (4), 256 threads.
// ---------------------------------------------------------------------------
__global__ void finalize_bn1(const float* __restrict__ g1,
                             const float* __restrict__ be1, int E)
{
    const int blk = blockIdx.x, t = threadIdx.x;
    __shared__ float sa[CC], sb[CC];
    if (t < CC) {
        float N = (float)E * (float)DD;
        float mean = g_stats1[blk * 2 * CC + t] / N;
        float var  = g_stats1[blk * 2 * CC + CC + t] / N - mean * mean;
        float a = g1[t] * rsqrtf(var + EPS_BN);
        sa[t] = a;
        sb[t] = be1[t] - mean * a;
    }
    __syncthreads();
    for (int k = t; k < CD; k += blockDim.x) {
        int c = k / DD;
        g_a1k[blk * CD + k] = sa[c];
        g_b1k[blk * CD + k] = sb[c];
    }
}

// ---------------------------------------------------------------------------
// K3: batched FC GEMM:  z[blk,e,n] = relu(a1k*y + b1k)[e,:] . fc_w[n,:] + fc_b[n]
// BM=64, BN=100, KT=16. 200 threads = 8 (m) x 25 (n); per-thread 8x4 tile,
// accumulated as 16 packed f32x2 FMAs per k-step.
// Grid: ((E+63)/64, 2, 4)
// ---------------------------------------------------------------------------
__global__ void __launch_bounds__(224)
fc_gemm(const float* __restrict__ fc_w, const float* __restrict__ fc_b, int E)
{
    const int blk = blockIdx.z;
    const int m0 = blockIdx.x * 64;
    const int n0 = blockIdx.y * 100;
    const int tid = threadIdx.x;
    const int tm = tid / 25;          // 0..7
    const int tn = tid % 25;          // 0..24

    __shared__ float As[16][64];
    __shared__ float Bs[16][100];

    const float* Ay  = g_y + (size_t)blk * E * CD;
    const float* a1k = g_a1k + blk * CD;
    const float* b1k = g_b1k + blk * CD;

    unsigned long long acc[4][4];
    #pragma unroll
    for (int i = 0; i < 4; i++)
        #pragma unroll
        for (int j = 0; j < 4; j++) acc[i][j] = pk2(0.f, 0.f);

    for (int kt = 0; kt < CD / 16; kt++) {
        const int k0 = kt * 16;
        // load A tile 64x16 (BN1 + ReLU applied on the fly)
        for (int i = tid; i < 1024; i += 200) {
            int r = i >> 4, j = i & 15;
            int k = k0 + j, row = m0 + r;
            float v = 0.f;
            if (row < E)
                v = fmaxf(fmaf(a1k[k], Ay[(size_t)row * CD + k], b1k[k]), 0.f);
            As[j][r] = v;
        }
        // load B tile 100x16
        for (int i = tid; i < 1600; i += 200) {
            int r = i >> 4, j = i & 15;
            Bs[j][r] = fc_w[(size_t)(n0 + r) * CD + (k0 + j)];
        }
        __syncthreads();

        #pragma unroll
        for (int kk = 0; kk < 16; kk++) {
            float4 a0 = *(const float4*)&As[kk][tm * 8];
            float4 a1 = *(const float4*)&As[kk][tm * 8 + 4];
            float4 bv = *(const float4*)&Bs[kk][tn * 4];
            unsigned long long Av[4], Bv[4];
            Av[0] = pk2(a0.x, a0.y); Av[1] = pk2(a0.z, a0.w);
            Av[2] = pk2(a1.x, a1.y); Av[3] = pk2(a1.z, a1.w);
            Bv[0] = pk2(bv.x, bv.x); Bv[1] = pk2(bv.y, bv.y);
            Bv[2] = pk2(bv.z, bv.z); Bv[3] = pk2(bv.w, bv.w);
            #pragma unroll
            for (int mj = 0; mj < 4; mj++)
                #pragma unroll
                for (int nn = 0; nn < 4; nn++)
                    fma2(acc[mj][nn], Av[mj], Bv[nn]);
        }
        __syncthreads();
    }

    // epilogue: + fc_b, store z
    #pragma unroll
    for (int mj = 0; mj < 4; mj++) {
        #pragma unroll
        for (int nn = 0; nn < 4; nn++) {
            float lo, hi;
            unpk2(acc[mj][nn], lo, hi);
            int row = m0 + tm * 8 + 2 * mj;
            int col = n0 + tn * 4 + nn;
            float fb = fc_b[col];
            if (row < E)     g_z[((size_t)blk * E + row) * DD + col] = lo + fb;
            if (row + 1 < E) g_z[((size_t)blk * E + row + 1) * DD + col] = hi + fb;
        }
    }
}

// ---------------------------------------------------------------------------
// K4: BN2 partial stats (per feature n over edges). Grid: ((E+255)/256, 4)
// ---------------------------------------------------------------------------
__global__ void bn2_partial(int E)
{
    const int blk = blockIdx.y;
    const int e0 = blockIdx.x * 256;
    const int t = threadIdx.x;
    if (t >= DD) return;
    float s = 0.f, q = 0.f;
    int eend = min(e0 + 256, E);
    for (int e = e0; e < eend; e++) {
        float v = g_z[((size_t)blk * E + e) * DD + t];
        s += v;
        q = fmaf(v, v, q);
    }
    atomicAdd(&g_stats2[blk * 2 * DD + t], s);
    atomicAdd(&g_stats2[blk * 2 * DD + DD + t], q);
}

// ---------------------------------------------------------------------------
// K5: BN2 apply + ReLU + cosine sims + scatter. One warp per edge.
// Grid: ((E+7)/8), 256 threads.
// ---------------------------------------------------------------------------
__global__ void score_kernel(const float* __restrict__ g2,
                             const float* __restrict__ be2,
                             const int* __restrict__ o,
                             float* __restrict__ out,
                             int E, long long nnodes)
{
    const int w = threadIdx.x >> 5;
    const int lane = threadIdx.x & 31;
    const int e = blockIdx.x * 8 + w;
    if (e >= E) return;

    float dts[3] = {0.f, 0.f, 0.f};
    float nx[3]  = {0.f, 0.f, 0.f};
    float nr = 0.f;
    const float invE = 1.f / (float)E;

    for (int n = lane; n < DD; n += 32) {
        float xb[4];
        #pragma unroll
        for (int b = 0; b < 4; b++) {
            float mean = g_stats2[b * 2 * DD + n] * invE;
            float var  = g_stats2[b * 2 * DD + DD + n] * invE - mean * mean;
            float a = g2[n] * rsqrtf(var + EPS_BN);
            float z = g_z[((size_t)b * E + e) * DD + n];
            xb[b] = fmaxf(fmaf(a, z - mean, be2[n]), 0.f);
        }
        float re = xb[3];
        #pragma unroll
        for (int b = 0; b < 3; b++) {
            dts[b] = fmaf(xb[b], re, dts[b]);
            nx[b]  = fmaf(xb[b], xb[b], nx[b]);
        }
        nr = fmaf(re, re, nr);
    }
    #pragma unroll
    for (int off = 16; off; off >>= 1) {
        #pragma unroll
        for (int b = 0; b < 3; b++) {
            dts[b] += __shfl_down_sync(0xffffffffu, dts[b], off);
            nx[b]  += __shfl_down_sync(0xffffffffu, nx[b],  off);
        }
        nr += __shfl_down_sync(0xffffffffu, nr, off);
    }
    if (lane == 0) {
        float c = 0.f;
        #pragma unroll
        for (int b = 0; b < 3; b++) {
            float den = fmaxf(sqrtf(nx[b]) * sqrtf(nr), EPS_COS);
            c += dts[b] / den;
        }
        out[(size_t)e * nnodes + o[e]] = c;
    }
}

// ---------------------------------------------------------------------------
// launch
// ---------------------------------------------------------------------------
extern "C" void kernel_launch(void* const* d_in, const int* in_sizes, int n_in,
                              void* d_out, int out_size)
{
    const float* pre_emb   = (const float*)d_in[0];
    const float* r_emb     = (const float*)d_in[1];
    const float* W2        = (const float*)d_in[2];
    const float* b2        = (const float*)d_in[3];
    const float* W3        = (const float*)d_in[4];
    const float* b3        = (const float*)d_in[5];
    const float* W4        = (const float*)d_in[6];
    const float* b4        = (const float*)d_in[7];
    const float* fc_w      = (const float*)d_in[8];
    const float* fc_b      = (const float*)d_in[9];
    const float* g1        = (const float*)d_in[10];
    const float* be1       = (const float*)d_in[11];
    const float* g2        = (const float*)d_in[12];
    const float* be2       = (const float*)d_in[13];
    const int*   src_ids   = (const int*)d_in[14];
    const int*   edge_type = (const int*)d_in[15];
    const int*   p1        = (const int*)d_in[16];
    const int*   p2        = (const int*)d_in[17];
    const int*   p3        = (const int*)d_in[18];
    const int*   o         = (const int*)d_in[19];

    const int E = in_sizes[14];
    const long long nnodes = (long long)out_size / E;
    float* out = (float*)d_out;

    zero_kernel<<<4096, 256>>>(out, (size_t)out_size);

    dim3 gc(E, 4);
    conv_bn_kernel<<<gc, 256>>>(pre_emb, r_emb, W2, b2, W3, b3, W4, b4,
                                src_ids, edge_type, p1, p2, p3, E);

    finalize_bn1<<<4, 256>>>(g1, be1, E);

    dim3 gg((E + 63) / 64, 2, 4);
    fc_gemm<<<gg, 200>>>(fc_w, fc_b, E);

    dim3 gp((E + 255) / 256, 4);
    bn2_partial<<<gp, 256>>>(E);

    score_kernel<<<(E + 7) / 8, 256>>>(g2, be2, o, out, E, nnodes);
}

// round 13
// speedup vs baseline: 2.6167x; 2.6167x over previous
#include <cuda_runtime.h>
#include <cuda_fp16.h>
#include <cstdint>

#define EMAX 2048
#define DD   200
#define CC   50
#define KDIM 10000
#define KPAD 10240
#define MROWS (4 * EMAX)
#define NPAD 208
#define KHALF (KPAD / 2)
#define CH_K 32
#define NCHK (KHALF / CH_K)
#define EPS_BN  1e-5f
#define EPS_COS 1e-8f

__device__ __align__(128) __half g_Ah[(size_t)MROWS * KPAD];
__device__ __align__(128) __half g_Al[(size_t)MROWS * KPAD];
__device__ __align__(128) __half g_Bh[(size_t)NPAD * KPAD];
__device__ __align__(128) __half g_Bl[(size_t)NPAD * KPAD];
__device__ float g_zp[2ull * MROWS * DD];
__device__ float g_stats1[4 * 2 * CC];
__device__ float g_stats2[4 * 2 * DD];
__device__ float g_sa[4 * CC];
__device__ float g_sb[4 * CC];

__device__ __forceinline__ uint32_t smem_u32(const void* p) {
    uint32_t a;
    asm("{ .reg .u64 t; cvta.to.shared.u64 t, %1; cvt.u32.u64 %0, t; }" : "=r"(a) : "l"(p));
    return a;
}
__device__ __forceinline__ void cp16(uint32_t dst, const void* src) {
    asm volatile("cp.async.cg.shared.global [%0], [%1], 16;" :: "r"(dst), "l"(src) : "memory");
}
#define CP_COMMIT() asm volatile("cp.async.commit_group;" ::: "memory")
#define CP_WAIT0()  asm volatile("cp.async.wait_group 0;" ::: "memory")
#define CP_WAIT1()  asm volatile("cp.async.wait_group 1;" ::: "memory")

__device__ __forceinline__ void ldsm4(uint32_t* r, uint32_t addr) {
    asm volatile("ldmatrix.sync.aligned.m8n8.x4.shared.b16 {%0,%1,%2,%3}, [%4];"
        : "=r"(r[0]), "=r"(r[1]), "=r"(r[2]), "=r"(r[3]) : "r"(addr));
}
__device__ __forceinline__ void ldsm2(uint32_t* r, uint32_t addr) {
    asm volatile("ldmatrix.sync.aligned.m8n8.x2.shared.b16 {%0,%1}, [%2];"
        : "=r"(r[0]), "=r"(r[1]) : "r"(addr));
}
__device__ __forceinline__ void mma16816(float* c, const uint32_t* a, const uint32_t* b) {
    asm volatile("mma.sync.aligned.m16n8k16.row.col.f32.f16.f16.f32 "
        "{%0,%1,%2,%3},{%4,%5,%6,%7},{%8,%9},{%0,%1,%2,%3};"
        : "+f"(c[0]), "+f"(c[1]), "+f"(c[2]), "+f"(c[3])
        : "r"(a[0]), "r"(a[1]), "r"(a[2]), "r"(a[3]), "r"(b[0]), "r"(b[1]));
}

// ---------------------------------------------------------------------------
__global__ void zero_kernel(float* __restrict__ out, size_t n) {
    size_t stride = (size_t)gridDim.x * blockDim.x;
    size_t i = (size_t)blockIdx.x * blockDim.x + threadIdx.x;
    size_t n4 = n >> 2;
    float4 z4 = make_float4(0.f, 0.f, 0.f, 0.f);
    float4* o4 = (float4*)out;
    for (size_t j = i; j < n4; j += stride) o4[j] = z4;
    for (size_t j = (n4 << 2) + i; j < n; j += stride) out[j] = 0.f;
    if (blockIdx.x == 0) {
        for (int j = threadIdx.x; j < 4 * 2 * CC; j += blockDim.x) g_stats1[j] = 0.f;
        for (int j = threadIdx.x; j < 4 * 2 * DD; j += blockDim.x) g_stats2[j] = 0.f;
    }
}

// ---------------------------------------------------------------------------
__global__ void bconv_kernel(const float* __restrict__ fc_w) {
    const int n = blockIdx.x;
    for (int k = threadIdx.x; k < KPAD; k += blockDim.x) {
        __half hi = __float2half_rn(0.f), lo = hi;
        if (n < DD && k < KDIM) {
            float w = fc_w[(size_t)n * KDIM + k];
            hi = __float2half_rn(w);
            lo = __float2half_rn(w - __half2float(hi));
        }
        g_Bh[(size_t)n * KPAD + k] = hi;
        g_Bl[(size_t)n * KPAD + k] = lo;
    }
}

// ---------------------------------------------------------------------------
__device__ __forceinline__ int conv_setup(
    int e, int blk, int t,
    const float* pre_emb, const float* r_emb,
    const float* W2, const float* b2, const float* W3, const float* b3,
    const float* W4, const float* b4,
    const int* src_ids, const int* edge_type, const int* p1,
    const int* p2, const int* p3,
    float (*xs)[DD + 2], float* ws, float* bs)
{
    int Cin;
    const float *Wp, *bp;
    int rel[3] = {0, 0, 0};
    if (blk == 0)      { Cin = 2; Wp = W2; bp = b2; rel[0] = p1[e]; }
    else if (blk == 1) { Cin = 3; Wp = W3; bp = b3; rel[0] = p2[2*e]; rel[1] = p2[2*e+1]; }
    else if (blk == 2) { Cin = 4; Wp = W4; bp = b4; rel[0] = p3[3*e]; rel[1] = p3[3*e+1]; rel[2] = p3[3*e+2]; }
    else               { Cin = 2; Wp = W2; bp = b2; rel[0] = edge_type[e]; }

    const int sidx = src_ids[e];
    for (int i = 0; i < Cin; i++) {
        const float* src = (i == 0) ? (pre_emb + (size_t)sidx * DD)
                                    : (r_emb + (size_t)rel[i-1] * DD);
        for (int d = t; d < DD; d += blockDim.x) xs[i][d + 1] = src[d];
    }
    if (t < 4) { xs[t][0] = 0.f; xs[t][DD + 1] = 0.f; }
    for (int i = t; i < CC * Cin * 3; i += blockDim.x) ws[i] = Wp[i];
    if (t < CC) bs[t] = bp[t];
    return Cin;
}

__device__ __forceinline__ float conv_val(int Cin, int c, int t,
                                          float (*xs)[DD + 2],
                                          const float* ws, const float* bs)
{
    const float* w = &ws[c * Cin * 3];
    float acc = bs[c];
    for (int i = 0; i < Cin; i++) {
        acc = fmaf(w[i*3 + 0], xs[i][t    ], acc);
        acc = fmaf(w[i*3 + 1], xs[i][t + 1], acc);
        acc = fmaf(w[i*3 + 2], xs[i][t + 2], acc);
    }
    return acc;
}

// ---------------------------------------------------------------------------
__global__ void stats_kernel(
    const float* __restrict__ pre_emb, const float* __restrict__ r_emb,
    const float* __restrict__ W2, const float* __restrict__ b2,
    const float* __restrict__ W3, const float* __restrict__ b3,
    const float* __restrict__ W4, const float* __restrict__ b4,
    const int* __restrict__ src_ids, const int* __restrict__ edge_type,
    const int* __restrict__ p1, const int* __restrict__ p2,
    const int* __restrict__ p3, int E)
{
    const int e = blockIdx.x, blk = blockIdx.y, t = threadIdx.x;
    __shared__ float xs[4][DD + 2];
    __shared__ float ws[CC * 4 * 3];
    __shared__ float bs[CC];
    __shared__ float ssum[CC], ssq[CC];
    if (t < CC) { ssum[t] = 0.f; ssq[t] = 0.f; }
    int Cin = conv_setup(e, blk, t, pre_emb, r_emb, W2, b2, W3, b3, W4, b4,
                         src_ids, edge_type, p1, p2, p3, xs, ws, bs);
    __syncthreads();

    for (int c = 0; c < CC; c++) {
        float val = (t < DD) ? conv_val(Cin, c, t, xs, ws, bs) : 0.f;
        float v = val, q = val * val;
        #pragma unroll
        for (int off = 16; off; off >>= 1) {
            v += __shfl_down_sync(0xffffffffu, v, off);
            q += __shfl_down_sync(0xffffffffu, q, off);
        }
        if ((t & 31) == 0) { atomicAdd(&ssum[c], v); atomicAdd(&ssq[c], q); }
    }
    __syncthreads();
    if (t < CC)          atomicAdd(&g_stats1[blk * 2 * CC + t], ssum[t]);
    else if (t < 2 * CC) atomicAdd(&g_stats1[blk * 2 * CC + t], ssq[t - CC]);
}

// ---------------------------------------------------------------------------
__global__ void finalize_bn1(const float* __restrict__ g1,
                             const float* __restrict__ be1, int E)
{
    const int blk = blockIdx.x, t = threadIdx.x;
    if (t < CC) {
        float N = (float)E * (float)DD;
        float mean = g_stats1[blk * 2 * CC + t] / N;
        float var  = g_stats1[blk * 2 * CC + CC + t] / N - mean * mean;
        float a = g1[t] * rsqrtf(var + EPS_BN);
        g_sa[blk * CC + t] = a;
        g_sb[blk * CC + t] = be1[t] - mean * a;
    }
}

// ---------------------------------------------------------------------------
__global__ void abuild_kernel(
    const float* __restrict__ pre_emb, const float* __restrict__ r_emb,
    const float* __restrict__ W2, const float* __restrict__ b2,
    const float* __restrict__ W3, const float* __restrict__ b3,
    const float* __restrict__ W4, const float* __restrict__ b4,
    const int* __restrict__ src_ids, const int* __restrict__ edge_type,
    const int* __restrict__ p1, const int* __restrict__ p2,
    const int* __restrict__ p3, int E)
{
    const int e = blockIdx.x, blk = blockIdx.y, t = threadIdx.x;
    __shared__ float xs[4][DD + 2];
    __shared__ float ws[CC * 4 * 3];
    __shared__ float bs[CC];
    __shared__ float sa[CC], sb[CC];
    if (t < CC) { sa[t] = g_sa[blk * CC + t]; sb[t] = g_sb[blk * CC + t]; }
    int Cin = conv_setup(e, blk, t, pre_emb, r_emb, W2, b2, W3, b3, W4, b4,
                         src_ids, edge_type, p1, p2, p3, xs, ws, bs);
    __syncthreads();

    const size_t row = (size_t)blk * E + e;
    __half* ah = g_Ah + row * KPAD;
    __half* al = g_Al + row * KPAD;
    if (t < DD) {
        for (int c = 0; c < CC; c++) {
            float y = conv_val(Cin, c, t, xs, ws, bs);
            float v = fmaxf(fmaf(sa[c], y, sb[c]), 0.f);
            __half hi = __float2half_rn(v);
            __half lo = __float2half_rn(v - __half2float(hi));
            ah[c * DD + t] = hi;
            al[c * DD + t] = lo;
        }
    }
    for (int k = KDIM + t; k < KPAD; k += blockDim.x) {
        __half z = __float2half_rn(0.f);
        ah[k] = z; al[k] = z;
    }
}

// ---------------------------------------------------------------------------
// HMMA GEMM: zp[ky] = A(64-row tile) x B(208) over K half ky; fp16 split,
// 3 passes AhBh+AhBl+AlBh; 2-stage cp.async pipeline. Grid: (MROWS/64, 2).
// ---------------------------------------------------------------------------
#define ASTR 40
#define S_AH 0
#define S_AL (64 * ASTR)
#define S_BH (2 * 64 * ASTR)
#define S_BL (S_BH + NPAD * ASTR)
#define STG_HALVES (S_BH + 2 * NPAD * ASTR)
#define GEMM_SMEM_BYTES (2 * STG_HALVES * 2)

struct BFrags { uint32_t v[13][2]; };

__device__ __forceinline__ void issue_chunk(int tid, int m0, size_t kb,
                                            uint32_t base)
{
    #pragma unroll 1
    for (int q = tid; q < 2176; q += 256) {
        uint32_t dst; const __half* src;
        if (q < 512) {
            int half = q >> 8, idx = q & 255;
            int r = idx >> 2, sg = idx & 3;
            const __half* g = half ? g_Al : g_Ah;
            src = g + (size_t)(m0 + r) * KPAD + kb + sg * 8;
            dst = base + (uint32_t)((half ? S_AL : S_AH) + r * ASTR + sg * 8) * 2;
        } else {
            int q2 = q - 512;
            int half = (q2 >= 832), idx = half ? q2 - 832 : q2;
            int r = idx >> 2, sg = idx & 3;
            const __half* g = half ? g_Bl : g_Bh;
            src = g + (size_t)r * KPAD + kb + sg * 8;
            dst = base + (uint32_t)((half ? S_BL : S_BH) + r * ASTR + sg * 8) * 2;
        }
        cp16(dst, src);
    }
    CP_COMMIT();
}

__global__ void __launch_bounds__(256, 1)
gemm_kernel(const float* __restrict__ fc_b)
{
    extern __shared__ __half smh[];
    const int tid = threadIdx.x;
    const int wid = tid >> 5, lane = tid & 31;
    const int m0 = blockIdx.x * 64;
    const int ky = blockIdx.y;
    const size_t kb0 = (size_t)ky * KHALF;
    const uint32_t sbase = smem_u32(smh);

    const int wm = (wid & 3) * 16;
    const int wn = (wid >> 2) * 104;

    float acc[13][4];
    #pragma unroll
    for (int j = 0; j < 13; j++)
        #pragma unroll
        for (int i = 0; i < 4; i++) acc[j][i] = 0.f;

    issue_chunk(tid, m0, kb0, sbase);
    for (int ch = 0; ch < NCHK; ch++) {
        if (ch + 1 < NCHK) {
            issue_chunk(tid, m0, kb0 + (size_t)(ch + 1) * CH_K,
                        sbase + (uint32_t)(((ch + 1) & 1) * STG_HALVES * 2));
            CP_WAIT1();
        } else {
            CP_WAIT0();
        }
        __syncthreads();

        const uint32_t base = sbase + (uint32_t)((ch & 1) * STG_HALVES * 2);
        #pragma unroll
        for (int kk = 0; kk < 2; kk++) {
            const int k16 = kk * 16;
            uint32_t ah[4], al[4];
            {
                int r = wm + (lane & 7) + ((lane & 8) ? 8 : 0);
                int c = k16 + ((lane & 16) ? 8 : 0);
                ldsm4(ah, base + (uint32_t)(S_AH + r * ASTR + c) * 2);
                ldsm4(al, base + (uint32_t)(S_AL + r * ASTR + c) * 2);
            }
            BFrags bh, bl;
            {
                int c = k16 + ((lane & 8) ? 8 : 0);
                #pragma unroll
                for (int j = 0; j < 12; j += 2) {
                    int r = wn + (j + (lane >> 4)) * 8 + (lane & 7);
                    uint32_t off = (uint32_t)(r * ASTR + c) * 2;
                    ldsm4(&bh.v[j][0], base + S_BH * 2 + off);
                    ldsm4(&bl.v[j][0], base + S_BL * 2 + off);
                }
                int r12 = wn + 96 + (lane & 7);
                uint32_t off12 = (uint32_t)(r12 * ASTR + c) * 2;
                ldsm2(&bh.v[12][0], base + S_BH * 2 + off12);
                ldsm2(&bl.v[12][0], base + S_BL * 2 + off12);
            }
            #pragma unroll
            for (int j = 0; j < 13; j++) {
                mma16816(acc[j], ah, bh.v[j]);
                mma16816(acc[j], ah, bl.v[j]);
                mma16816(acc[j], al, bh.v[j]);
            }
        }
        __syncthreads();
    }

    // epilogue: partials to g_zp (fc_b added on ky==0 only)
    float* zp = g_zp + (size_t)ky * MROWS * DD;
    const int r0 = m0 + wm + (lane >> 2);
    #pragma unroll
    for (int j = 0; j < 13; j++) {
        int n0 = wn + j * 8 + (lane & 3) * 2;
        if (n0 < DD) {
            float b0 = (ky == 0) ? fc_b[n0] : 0.f;
            float b1 = (ky == 0) ? fc_b[n0 + 1] : 0.f;
            zp[(size_t)r0 * DD + n0]           = acc[j][0] + b0;
            zp[(size_t)r0 * DD + n0 + 1]       = acc[j][1] + b1;
            zp[(size_t)(r0 + 8) * DD + n0]     = acc[j][2] + b0;
            zp[(size_t)(r0 + 8) * DD + n0 + 1] = acc[j][3] + b1;
        }
    }
}

// ---------------------------------------------------------------------------
__global__ void bn2_partial(int E)
{
    const int blk = blockIdx.y;
    const int e0 = blockIdx.x * 256;
    const int t = threadIdx.x;
    if (t >= DD) return;
    float s = 0.f, q = 0.f;
    int eend = min(e0 + 256, E);
    for (int e = e0; e < eend; e++) {
        size_t idx = ((size_t)blk * E + e) * DD + t;
        float v = g_zp[idx] + g_zp[(size_t)MROWS * DD + idx];
        s += v;
        q = fmaf(v, v, q);
    }
    atomicAdd(&g_stats2[blk * 2 * DD + t], s);
    atomicAdd(&g_stats2[blk * 2 * DD + DD + t], q);
}

// ---------------------------------------------------------------------------
__global__ void score_kernel(const float* __restrict__ g2,
                             const float* __restrict__ be2,
                             const int* __restrict__ o,
                             float* __restrict__ out,
                             int E, long long nnodes)
{
    const int w = threadIdx.x >> 5;
    const int lane = threadIdx.x & 31;
    const int e = blockIdx.x * 8 + w;
    if (e >= E) return;

    float dts[3] = {0.f, 0.f, 0.f};
    float nx[3]  = {0.f, 0.f, 0.f};
    float nr = 0.f;
    const float invE = 1.f / (float)E;

    for (int n = lane; n < DD; n += 32) {
        float xb[4];
        #pragma unroll
        for (int b = 0; b < 4; b++) {
            float mean = g_stats2[b * 2 * DD + n] * invE;
            float var  = g_stats2[b * 2 * DD + DD + n] * invE - mean * mean;
            float a = g2[n] * rsqrtf(var + EPS_BN);
            size_t idx = ((size_t)b * E + e) * DD + n;
            float z = g_zp[idx] + g_zp[(size_t)MROWS * DD + idx];
            xb[b] = fmaxf(fmaf(a, z - mean, be2[n]), 0.f);
        }
        float re = xb[3];
        #pragma unroll
        for (int b = 0; b < 3; b++) {
            dts[b] = fmaf(xb[b], re, dts[b]);
            nx[b]  = fmaf(xb[b], xb[b], nx[b]);
        }
        nr = fmaf(re, re, nr);
    }
    #pragma unroll
    for (int off = 16; off; off >>= 1) {
        #pragma unroll
        for (int b = 0; b < 3; b++) {
            dts[b] += __shfl_down_sync(0xffffffffu, dts[b], off);
            nx[b]  += __shfl_down_sync(0xffffffffu, nx[b],  off);
        }
        nr += __shfl_down_sync(0xffffffffu, nr, off);
    }
    if (lane == 0) {
        float c = 0.f;
        #pragma unroll
        for (int b = 0; b < 3; b++) {
            float den = fmaxf(sqrtf(nx[b]) * sqrtf(nr), EPS_COS);
            c += dts[b] / den;
        }
        out[(size_t)e * nnodes + o[e]] = c;
    }
}

// ---------------------------------------------------------------------------
extern "C" void kernel_launch(void* const* d_in, const int* in_sizes, int n_in,
                              void* d_out, int out_size)
{
    const float* pre_emb   = (const float*)d_in[0];
    const float* r_emb     = (const float*)d_in[1];
    const float* W2        = (const float*)d_in[2];
    const float* b2        = (const float*)d_in[3];
    const float* W3        = (const float*)d_in[4];
    const float* b3        = (const float*)d_in[5];
    const float* W4        = (const float*)d_in[6];
    const float* b4        = (const float*)d_in[7];
    const float* fc_w      = (const float*)d_in[8];
    const float* fc_b      = (const float*)d_in[9];
    const float* g1        = (const float*)d_in[10];
    const float* be1       = (const float*)d_in[11];
    const float* g2        = (const float*)d_in[12];
    const float* be2       = (const float*)d_in[13];
    const int*   src_ids   = (const int*)d_in[14];
    const int*   edge_type = (const int*)d_in[15];
    const int*   p1        = (const int*)d_in[16];
    const int*   p2        = (const int*)d_in[17];
    const int*   p3        = (const int*)d_in[18];
    const int*   o         = (const int*)d_in[19];

    const int E = in_sizes[14];
    const long long nnodes = (long long)out_size / E;
    float* out = (float*)d_out;

    cudaFuncSetAttribute(gemm_kernel,
                         cudaFuncAttributeMaxDynamicSharedMemorySize,
                         GEMM_SMEM_BYTES);

    zero_kernel<<<4096, 256>>>(out, (size_t)out_size);

    bconv_kernel<<<NPAD, 256>>>(fc_w);

    dim3 gc(E, 4);
    stats_kernel<<<gc, 256>>>(pre_emb, r_emb, W2, b2, W3, b3, W4, b4,
                              src_ids, edge_type, p1, p2, p3, E);

    finalize_bn1<<<4, 64>>>(g1, be1, E);

    abuild_kernel<<<gc, 256>>>(pre_emb, r_emb, W2, b2, W3, b3, W4, b4,
                               src_ids, edge_type, p1, p2, p3, E);

    dim3 gg((4 * E) / 64, 2);
    gemm_kernel<<<gg, 256, GEMM_SMEM_BYTES>>>(fc_b);

    dim3 gp((E + 255) / 256, 4);
    bn2_partial<<<gp, 256>>>(E);

    score_kernel<<<(E + 7) / 8, 256>>>(g2, be2, o, out, E, nnodes);
}